// round 3
// baseline (speedup 1.0000x reference)
#include <cuda_runtime.h>

#define NT 256
#define L_IN 4096
#define DZV 30
#define CV 10
#define NPG 15
#define B_TOT 512

__constant__ float cW1[DZV*96];   // [d][oc<4][ch<8][k<3]
__constant__ float cB1[DZV*4];
__constant__ float cW2[DZV*96];   // [d][oc<8][ch<4][k<3]
__constant__ float cB2[DZV*8];
__constant__ float cW3[DZV*192];  // [d][oc<8][ch<8][k<3]
__constant__ float cB3[DZV*8];
__constant__ float cWh[DZV*80];   // [d][c][j]
__constant__ float cZ[DZV];

// out[b,c] = sum_d z[d]*bh[d,c]  (head bias folded here)
__global__ void init_out_kernel(const float* __restrict__ z,
                                const float* __restrict__ bh,
                                float* __restrict__ out) {
    int i = blockIdx.x * blockDim.x + threadIdx.x;
    if (i < B_TOT*CV) {
        int c = i % CV;
        float s = 0.f;
        #pragma unroll
        for (int d = 0; d < DZV; d++) s = fmaf(z[d], bh[d*CV + c], s);
        out[i] = s;
    }
}

// ---------------- smem layout (half-sequence chunk) ----------------
#define XS_STR 2064
#define H1_STR 1032
#define H2_STR 520
#define H1_OFF (8*XS_STR)                 // 16512
#define H2_OFF (H1_OFF + 4*H1_STR)        // 20640
#define RED_OFF (H2_OFF + 8*H2_STR)       // 24800
#define SMEM_FLOATS (RED_OFF + 64)        // 24864 floats = 99456 B

__global__ __launch_bounds__(NT, 2)
void ensemble_kernel(const int* __restrict__ ids,
                     const float* __restrict__ mask,
                     const float* __restrict__ embed,
                     float* __restrict__ out)
{
    extern __shared__ float sm[];
    float* xs  = sm;               // [8][XS_STR]
    float* h1  = sm + H1_OFF;      // [4][H1_STR]
    float* h2  = sm + H2_OFF;      // [8][H2_STR]
    float* red = sm + RED_OFF;     // [8 warps][8]

    const int tid  = threadIdx.x;
    const int lane = tid & 31;
    const int warp = tid >> 5;
    const int b    = blockIdx.x;
    const int ck   = blockIdx.y;   // sequence chunk 0/1
    const int g    = blockIdx.z;   // net group 0/1

    // chunk ranges: conv3 out p, conv2 out q, conv1 out r, input x (local counts)
    const int p_cnt = ck ? 510 : 511;
    const int q_cnt = ck ? 512 : 513;
    const int r_cnt = ck ? 1025 : 1027;
    const int x_lo  = ck ? 2044 : 0;
    const int x_cnt = ck ? 2051 : 2055;

    // ---- gather masked embeddings for this chunk, channel-major ----
    #pragma unroll 1
    for (int i = tid; i < x_cnt; i += NT) {
        int gi = x_lo + i;
        int   id = __ldg(&ids[b*L_IN + gi]);
        float m  = __ldg(&mask[b*L_IN + gi]);
        float4 e0 = __ldg((const float4*)(embed + (size_t)id*8));
        float4 e1 = __ldg((const float4*)(embed + (size_t)id*8 + 4));
        xs[0*XS_STR+i] = e0.x*m; xs[1*XS_STR+i] = e0.y*m;
        xs[2*XS_STR+i] = e0.z*m; xs[3*XS_STR+i] = e0.w*m;
        xs[4*XS_STR+i] = e1.x*m; xs[5*XS_STR+i] = e1.y*m;
        xs[6*XS_STR+i] = e1.z*m; xs[7*XS_STR+i] = e1.w*m;
    }
    __syncthreads();

    float oacc = 0.f;   // warp0, lane<CV

    #pragma unroll 1
    for (int dn = 0; dn < NPG; dn++) {
        const int d = g*NPG + dn;

        // ======== conv1: xs[8][*] -> h1[4][r_cnt], K3 S2 + ReLU ========
        {
            float w[96];
            #pragma unroll
            for (int i = 0; i < 96; i++) w[i] = cW1[d*96 + i];
            float bb[4];
            #pragma unroll
            for (int i = 0; i < 4; i++) bb[i] = cB1[d*4 + i];

            #pragma unroll 1
            for (int it = 0; it < 2; it++) {
                const int r0 = (it*NT + tid) * 4;
                if (r0 >= r_cnt) break;
                const int ib = 2*r0;
                float acc[4][4];
                #pragma unroll
                for (int pos = 0; pos < 4; pos++)
                    #pragma unroll
                    for (int oc = 0; oc < 4; oc++) acc[pos][oc] = bb[oc];

                #pragma unroll
                for (int ch = 0; ch < 8; ch++) {
                    const float* row = xs + ch*XS_STR + ib;
                    float4 v0 = *(const float4*)row;
                    float4 v1 = *(const float4*)(row + 4);
                    float  v8 = row[8];
                    float win[9] = {v0.x,v0.y,v0.z,v0.w, v1.x,v1.y,v1.z,v1.w, v8};
                    #pragma unroll
                    for (int pos = 0; pos < 4; pos++) {
                        #pragma unroll
                        for (int k = 0; k < 3; k++) {
                            const float xv = win[2*pos + k];
                            #pragma unroll
                            for (int oc = 0; oc < 4; oc++)
                                acc[pos][oc] = fmaf(w[(oc*8+ch)*3+k], xv, acc[pos][oc]);
                        }
                    }
                }
                if (r0 + 3 < r_cnt) {
                    #pragma unroll
                    for (int oc = 0; oc < 4; oc++)
                        *(float4*)(h1 + oc*H1_STR + r0) =
                            make_float4(fmaxf(acc[0][oc],0.f), fmaxf(acc[1][oc],0.f),
                                        fmaxf(acc[2][oc],0.f), fmaxf(acc[3][oc],0.f));
                } else {
                    #pragma unroll
                    for (int pos = 0; pos < 4; pos++)
                        if (r0 + pos < r_cnt)
                            #pragma unroll
                            for (int oc = 0; oc < 4; oc++)
                                h1[oc*H1_STR + r0 + pos] = fmaxf(acc[pos][oc], 0.f);
                }
            }
        }
        __syncthreads();

        // ======== conv2: h1[4][*] -> h2[8][q_cnt], K3 S2 + ReLU ========
        {
            float w[96];
            #pragma unroll
            for (int i = 0; i < 96; i++) w[i] = cW2[d*96 + i];
            float bb[8];
            #pragma unroll
            for (int i = 0; i < 8; i++) bb[i] = cB2[d*8 + i];

            #pragma unroll 1
            for (int it = 0; it < 2; it++) {
                const int q0 = (it*NT + tid) * 2;
                if (q0 >= q_cnt) break;
                const int ib = 2*q0;
                float acc[2][8];
                #pragma unroll
                for (int pos = 0; pos < 2; pos++)
                    #pragma unroll
                    for (int oc = 0; oc < 8; oc++) acc[pos][oc] = bb[oc];

                #pragma unroll
                for (int ch = 0; ch < 4; ch++) {
                    const float* row = h1 + ch*H1_STR + ib;
                    float4 v0 = *(const float4*)row;
                    float  v4 = row[4];
                    float win[5] = {v0.x,v0.y,v0.z,v0.w, v4};
                    #pragma unroll
                    for (int pos = 0; pos < 2; pos++) {
                        #pragma unroll
                        for (int k = 0; k < 3; k++) {
                            const float xv = win[2*pos + k];
                            #pragma unroll
                            for (int oc = 0; oc < 8; oc++)
                                acc[pos][oc] = fmaf(w[(oc*4+ch)*3+k], xv, acc[pos][oc]);
                        }
                    }
                }
                if (q0 + 1 < q_cnt) {
                    #pragma unroll
                    for (int oc = 0; oc < 8; oc++)
                        *(float2*)(h2 + oc*H2_STR + q0) =
                            make_float2(fmaxf(acc[0][oc],0.f), fmaxf(acc[1][oc],0.f));
                } else {
                    #pragma unroll
                    for (int oc = 0; oc < 8; oc++)
                        h2[oc*H2_STR + q0] = fmaxf(acc[0][oc], 0.f);
                }
            }
        }
        __syncthreads();

        // ======== conv3 + ReLU + pool partial: h2[8][*] -> psum[8] ========
        float psum[8];
        #pragma unroll
        for (int i = 0; i < 8; i++) psum[i] = 0.f;
        {
            const int p0 = tid * 2;
            if (p0 < p_cnt) {
                #pragma unroll
                for (int half = 0; half < 2; half++) {
                    float w[96];
                    #pragma unroll
                    for (int i = 0; i < 96; i++) w[i] = cW3[d*192 + half*96 + i];
                    float bb[4];
                    #pragma unroll
                    for (int i = 0; i < 4; i++) bb[i] = cB3[d*8 + half*4 + i];

                    float acc[2][4];
                    #pragma unroll
                    for (int pos = 0; pos < 2; pos++)
                        #pragma unroll
                        for (int oc = 0; oc < 4; oc++) acc[pos][oc] = bb[oc];

                    #pragma unroll
                    for (int ch = 0; ch < 8; ch++) {
                        const float* row = h2 + ch*H2_STR + p0;
                        float2 a0 = *(const float2*)row;
                        float2 a1 = *(const float2*)(row + 2);
                        float win[4] = {a0.x, a0.y, a1.x, a1.y};
                        #pragma unroll
                        for (int pos = 0; pos < 2; pos++) {
                            #pragma unroll
                            for (int k = 0; k < 3; k++) {
                                const float xv = win[pos + k];
                                #pragma unroll
                                for (int oc = 0; oc < 4; oc++)
                                    acc[pos][oc] = fmaf(w[(oc*8+ch)*3+k], xv, acc[pos][oc]);
                            }
                        }
                    }
                    #pragma unroll
                    for (int pos = 0; pos < 2; pos++)
                        if (p0 + pos < p_cnt)
                            #pragma unroll
                            for (int oc = 0; oc < 4; oc++)
                                psum[half*4 + oc] += fmaxf(acc[pos][oc], 0.f);
                }
            }
        }

        // ---- warp reduce psum -> red[warp][oc] ----
        #pragma unroll
        for (int oc = 0; oc < 8; oc++) {
            float s = psum[oc];
            #pragma unroll
            for (int off = 16; off > 0; off >>= 1)
                s += __shfl_down_sync(0xFFFFFFFFu, s, off);
            if (lane == 0) red[warp*8 + oc] = s;
        }
        __syncthreads();

        // ---- warp0: cross-warp reduce + head matvec (parallel over lanes) ----
        if (warp == 0) {
            float s = red[lane] + red[lane + 32];   // lane = wv*8+oc for wv<4
            s += __shfl_xor_sync(0xFFFFFFFFu, s, 8);
            s += __shfl_xor_sync(0xFFFFFFFFu, s, 16);
            float pj[8];
            #pragma unroll
            for (int j = 0; j < 8; j++)
                pj[j] = __shfl_sync(0xFFFFFFFFu, s, j);
            if (lane < CV) {
                float v = 0.f;
                #pragma unroll
                for (int j = 0; j < 8; j++)
                    v = fmaf(pj[j], cWh[(d*CV + lane)*8 + j], v);
                oacc = fmaf(v, cZ[d] * (1.0f/1021.0f), oacc);
            }
        }
        // red hazard: next write to red only after conv1+conv2 barriers of the
        // next net, which warp0 must also pass after its read above.
    }

    if (warp == 0 && lane < CV)
        atomicAdd(&out[b*CV + lane], oacc);
}

extern "C" void kernel_launch(void* const* d_in, const int* in_sizes, int n_in,
                              void* d_out, int out_size) {
    const int*   ids  = (const int*)  d_in[0];
    const float* mask = (const float*)d_in[1];
    const float* z    = (const float*)d_in[2];
    const float* emb  = (const float*)d_in[3];
    const float* W1   = (const float*)d_in[4];
    const float* b1   = (const float*)d_in[5];
    const float* W2   = (const float*)d_in[6];
    const float* b2   = (const float*)d_in[7];
    const float* W3   = (const float*)d_in[8];
    const float* b3   = (const float*)d_in[9];
    const float* Wh   = (const float*)d_in[10];
    const float* bh   = (const float*)d_in[11];
    float* out = (float*)d_out;

    cudaMemcpyToSymbolAsync(cW1, W1, DZV*96*sizeof(float),  0, cudaMemcpyDeviceToDevice, 0);
    cudaMemcpyToSymbolAsync(cB1, b1, DZV*4*sizeof(float),   0, cudaMemcpyDeviceToDevice, 0);
    cudaMemcpyToSymbolAsync(cW2, W2, DZV*96*sizeof(float),  0, cudaMemcpyDeviceToDevice, 0);
    cudaMemcpyToSymbolAsync(cB2, b2, DZV*8*sizeof(float),   0, cudaMemcpyDeviceToDevice, 0);
    cudaMemcpyToSymbolAsync(cW3, W3, DZV*192*sizeof(float), 0, cudaMemcpyDeviceToDevice, 0);
    cudaMemcpyToSymbolAsync(cB3, b3, DZV*8*sizeof(float),   0, cudaMemcpyDeviceToDevice, 0);
    cudaMemcpyToSymbolAsync(cWh, Wh, DZV*80*sizeof(float),  0, cudaMemcpyDeviceToDevice, 0);
    cudaMemcpyToSymbolAsync(cZ,  z,  DZV*sizeof(float),     0, cudaMemcpyDeviceToDevice, 0);

    init_out_kernel<<<(B_TOT*CV + 255)/256, 256>>>(z, bh, out);

    cudaFuncSetAttribute(ensemble_kernel,
                         cudaFuncAttributeMaxDynamicSharedMemorySize,
                         SMEM_FLOATS * (int)sizeof(float));
    ensemble_kernel<<<dim3(B_TOT, 2, 2), NT, SMEM_FLOATS * (int)sizeof(float)>>>(ids, mask, emb, out);
}

// round 4
// speedup vs baseline: 1.1888x; 1.1888x over previous
#include <cuda_runtime.h>

#define NT 512
#define L_IN 4096
#define DZV 30
#define CV 10
#define NPG 15
#define B_TOT 512

typedef unsigned long long u64;

// ---- paired weights: u64 = (oc_even, oc_odd) float pair ----
__constant__ u64  cW1p[DZV*48];   // [d][ch<8][k<3][pr<2]
__constant__ u64  cW2p[DZV*48];   // [d][ch<4][k<3][pr<4]
__constant__ u64  cW3p[DZV*96];   // [d][ch<8][k<3][pr<4]
__constant__ u64  cB1p[DZV*2];
__constant__ u64  cB2p[DZV*4];
__constant__ u64  cB3p[DZV*4];
__constant__ float cWh[DZV*80];   // [d][c][j]
__constant__ float cZ[DZV];

__device__ float g_wscratch[11520];

__device__ __forceinline__ u64 dup2(float v) {
    u64 r; asm("mov.b64 %0, {%1, %1};" : "=l"(r) : "f"(v)); return r;
}
__device__ __forceinline__ void unpack2(u64 v, float& lo, float& hi) {
    asm("mov.b64 {%0, %1}, %2;" : "=f"(lo), "=f"(hi) : "l"(v));
}
__device__ __forceinline__ u64 ffma2(u64 a, u64 b, u64 c) {
    u64 d; asm("fma.rn.f32x2 %0, %1, %2, %3;" : "=l"(d) : "l"(a), "l"(b), "l"(c)); return d;
}

// repack scalar conv weights into oc-paired float layout
__global__ void repack_kernel(const float* __restrict__ W1,
                              const float* __restrict__ W2,
                              const float* __restrict__ W3) {
    int i = blockIdx.x * blockDim.x + threadIdx.x;
    if (i < DZV*96) {   // W1p: dst ((d*8+ch)*3+k)*2+pr pair-half h
        int d = i / 96, r = i % 96;
        int h = r & 1, pr = (r >> 1) & 1, k = (r >> 2) % 3, ch = (r >> 2) / 3;
        int oc = 2*pr + h;
        g_wscratch[i] = W1[d*96 + oc*24 + ch*3 + k];
    }
    if (i < DZV*96) {   // W2p
        int d = i / 96, r = i % 96;
        int h = r & 1, pr = (r >> 1) & 3, k = (r >> 3) % 3, ch = (r >> 3) / 3;
        int oc = 2*pr + h;
        g_wscratch[2880 + i] = W2[d*96 + oc*12 + ch*3 + k];
    }
    if (i < DZV*192) {  // W3p
        int d = i / 192, r = i % 192;
        int h = r & 1, pr = (r >> 1) & 3, k = (r >> 3) % 3, ch = (r >> 3) / 3;
        int oc = 2*pr + h;
        g_wscratch[5760 + i] = W3[d*192 + oc*24 + ch*3 + k];
    }
}

// out[b,c] = sum_d z[d]*bh[d,c]  (head bias folded here)
__global__ void init_out_kernel(const float* __restrict__ z,
                                const float* __restrict__ bh,
                                float* __restrict__ out) {
    int i = blockIdx.x * blockDim.x + threadIdx.x;
    if (i < B_TOT*CV) {
        int c = i % CV;
        float s = 0.f;
        #pragma unroll
        for (int d = 0; d < DZV; d++) s = fmaf(z[d], bh[d*CV + c], s);
        out[i] = s;
    }
}

// ---- smem layout: full sequence, 1 CTA/SM ----
#define XS_STR 4104
#define H1_STR 2056
#define H2_STR 1032
#define H1_OFF (8*XS_STR)                 // 32832
#define H2_OFF (H1_OFF + 4*H1_STR)        // 41056
#define RED_OFF (H2_OFF + 8*H2_STR)       // 49312
#define SMEM_FLOATS (RED_OFF + 136)       // 49448 floats = 197792 B

__global__ __launch_bounds__(NT, 1)
void ensemble_kernel(const int* __restrict__ ids,
                     const float* __restrict__ mask,
                     const float* __restrict__ embed,
                     float* __restrict__ out)
{
    extern __shared__ float sm[];
    float* xs  = sm;               // [8][XS_STR]
    float* h1  = sm + H1_OFF;      // [4][H1_STR]
    float* h2  = sm + H2_OFF;      // [8][H2_STR]
    float* red = sm + RED_OFF;     // [16 warps][8]

    const int tid  = threadIdx.x;
    const int lane = tid & 31;
    const int warp = tid >> 5;
    const int b    = blockIdx.x;
    const int g    = blockIdx.y;

    // zero the xs tail pad touched by the (discarded) OOB conv1 position
    if (tid < 8) {
        #pragma unroll
        for (int ch = 0; ch < 8; ch++) xs[ch*XS_STR + 4096 + tid] = 0.f;
    }

    // ---- gather masked embeddings, channel-major ----
    #pragma unroll 1
    for (int i = tid; i < L_IN; i += NT) {
        int   id = __ldg(&ids[b*L_IN + i]);
        float m  = __ldg(&mask[b*L_IN + i]);
        float4 e0 = __ldg((const float4*)(embed + (size_t)id*8));
        float4 e1 = __ldg((const float4*)(embed + (size_t)id*8 + 4));
        xs[0*XS_STR+i] = e0.x*m; xs[1*XS_STR+i] = e0.y*m;
        xs[2*XS_STR+i] = e0.z*m; xs[3*XS_STR+i] = e0.w*m;
        xs[4*XS_STR+i] = e1.x*m; xs[5*XS_STR+i] = e1.y*m;
        xs[6*XS_STR+i] = e1.z*m; xs[7*XS_STR+i] = e1.w*m;
    }
    __syncthreads();

    float oacc = 0.f;   // warp0, lane<CV

    #pragma unroll 1
    for (int dn = 0; dn < NPG; dn++) {
        const int d = g*NPG + dn;

        // ======== conv1: xs[8][4096] -> h1[4][2047], K3 S2 + ReLU ========
        // 4 positions/thread, single pass (512*4 = 2048; pos 2047 is dead pad)
        {
            const int r0 = tid * 4;
            const int ib = r0 * 2;
            u64 acc[4][2];
            {
                const u64 bb0 = cB1p[d*2+0], bb1 = cB1p[d*2+1];
                #pragma unroll
                for (int p = 0; p < 4; p++) { acc[p][0] = bb0; acc[p][1] = bb1; }
            }
            #pragma unroll
            for (int ch = 0; ch < 8; ch++) {
                const float* row = xs + ch*XS_STR + ib;
                float4 v0 = *(const float4*)row;
                float4 v1 = *(const float4*)(row + 4);
                float  v8 = row[8];
                u64 X[9];
                X[0]=dup2(v0.x); X[1]=dup2(v0.y); X[2]=dup2(v0.z); X[3]=dup2(v0.w);
                X[4]=dup2(v1.x); X[5]=dup2(v1.y); X[6]=dup2(v1.z); X[7]=dup2(v1.w);
                X[8]=dup2(v8);
                #pragma unroll
                for (int p = 0; p < 4; p++) {
                    #pragma unroll
                    for (int k = 0; k < 3; k++) {
                        const u64 x2 = X[2*p + k];
                        acc[p][0] = ffma2(cW1p[d*48 + (ch*3+k)*2 + 0], x2, acc[p][0]);
                        acc[p][1] = ffma2(cW1p[d*48 + (ch*3+k)*2 + 1], x2, acc[p][1]);
                    }
                }
            }
            float o[4][4];
            #pragma unroll
            for (int p = 0; p < 4; p++) {
                float a0,a1,a2,a3;
                unpack2(acc[p][0], a0, a1);
                unpack2(acc[p][1], a2, a3);
                o[p][0]=fmaxf(a0,0.f); o[p][1]=fmaxf(a1,0.f);
                o[p][2]=fmaxf(a2,0.f); o[p][3]=fmaxf(a3,0.f);
            }
            #pragma unroll
            for (int oc = 0; oc < 4; oc++)
                *(float4*)(h1 + oc*H1_STR + r0) =
                    make_float4(o[0][oc], o[1][oc], o[2][oc], o[3][oc]);
        }
        __syncthreads();

        // ======== conv2: h1[4][2047] -> h2[8][1023], K3 S2 + ReLU ========
        // 2 positions/thread, single pass (512*2 = 1024; pos 1023 dead pad)
        {
            const int q0 = tid * 2;
            const int ib = q0 * 2;
            u64 acc[2][4];
            {
                u64 bb[4];
                #pragma unroll
                for (int i = 0; i < 4; i++) bb[i] = cB2p[d*4+i];
                #pragma unroll
                for (int p = 0; p < 2; p++)
                    #pragma unroll
                    for (int pr = 0; pr < 4; pr++) acc[p][pr] = bb[pr];
            }
            #pragma unroll
            for (int ch = 0; ch < 4; ch++) {
                const float* row = h1 + ch*H1_STR + ib;
                float4 v0 = *(const float4*)row;
                float  v4 = row[4];
                u64 X[5];
                X[0]=dup2(v0.x); X[1]=dup2(v0.y); X[2]=dup2(v0.z); X[3]=dup2(v0.w);
                X[4]=dup2(v4);
                #pragma unroll
                for (int p = 0; p < 2; p++) {
                    #pragma unroll
                    for (int k = 0; k < 3; k++) {
                        const u64 x2 = X[2*p + k];
                        #pragma unroll
                        for (int pr = 0; pr < 4; pr++)
                            acc[p][pr] = ffma2(cW2p[d*48 + (ch*3+k)*4 + pr], x2, acc[p][pr]);
                    }
                }
            }
            float o[2][8];
            #pragma unroll
            for (int p = 0; p < 2; p++)
                #pragma unroll
                for (int pr = 0; pr < 4; pr++) {
                    float lo, hi;
                    unpack2(acc[p][pr], lo, hi);
                    o[p][2*pr+0] = fmaxf(lo, 0.f);
                    o[p][2*pr+1] = fmaxf(hi, 0.f);
                }
            #pragma unroll
            for (int oc = 0; oc < 8; oc++)
                *(float2*)(h2 + oc*H2_STR + q0) = make_float2(o[0][oc], o[1][oc]);
        }
        __syncthreads();

        // ======== conv3 + ReLU + pool partial: h2[8][1023] -> psum[8] ========
        // 2 positions/thread (pos >= 1021 masked out of the pool)
        float psum[8];
        #pragma unroll
        for (int i = 0; i < 8; i++) psum[i] = 0.f;
        {
            const int p0 = tid * 2;
            u64 acc[2][4];
            {
                u64 bb[4];
                #pragma unroll
                for (int i = 0; i < 4; i++) bb[i] = cB3p[d*4+i];
                #pragma unroll
                for (int p = 0; p < 2; p++)
                    #pragma unroll
                    for (int pr = 0; pr < 4; pr++) acc[p][pr] = bb[pr];
            }
            #pragma unroll
            for (int ch = 0; ch < 8; ch++) {
                const float* row = h2 + ch*H2_STR + p0;
                float2 a0 = *(const float2*)row;
                float2 a1 = *(const float2*)(row + 2);
                u64 X[4];
                X[0]=dup2(a0.x); X[1]=dup2(a0.y); X[2]=dup2(a1.x); X[3]=dup2(a1.y);
                #pragma unroll
                for (int p = 0; p < 2; p++) {
                    #pragma unroll
                    for (int k = 0; k < 3; k++) {
                        const u64 x2 = X[p + k];
                        #pragma unroll
                        for (int pr = 0; pr < 4; pr++)
                            acc[p][pr] = ffma2(cW3p[d*96 + (ch*3+k)*4 + pr], x2, acc[p][pr]);
                    }
                }
            }
            #pragma unroll
            for (int p = 0; p < 2; p++) {
                if (p0 + p < 1021) {
                    #pragma unroll
                    for (int pr = 0; pr < 4; pr++) {
                        float lo, hi;
                        unpack2(acc[p][pr], lo, hi);
                        psum[2*pr+0] += fmaxf(lo, 0.f);
                        psum[2*pr+1] += fmaxf(hi, 0.f);
                    }
                }
            }
        }

        // ---- warp reduce psum -> red[warp][oc] ----
        #pragma unroll
        for (int oc = 0; oc < 8; oc++) {
            float s = psum[oc];
            #pragma unroll
            for (int off = 16; off > 0; off >>= 1)
                s += __shfl_down_sync(0xFFFFFFFFu, s, off);
            if (lane == 0) red[warp*8 + oc] = s;
        }
        __syncthreads();

        // ---- warp0: cross-warp reduce (16 warps) + head matvec ----
        if (warp == 0) {
            float s = red[lane] + red[lane+32] + red[lane+64] + red[lane+96];
            s += __shfl_xor_sync(0xFFFFFFFFu, s, 8);
            s += __shfl_xor_sync(0xFFFFFFFFu, s, 16);
            float pj[8];
            #pragma unroll
            for (int j = 0; j < 8; j++)
                pj[j] = __shfl_sync(0xFFFFFFFFu, s, j);
            if (lane < CV) {
                float v = 0.f;
                #pragma unroll
                for (int j = 0; j < 8; j++)
                    v = fmaf(pj[j], cWh[(d*CV + lane)*8 + j], v);
                oacc = fmaf(v, cZ[d] * (1.0f/1021.0f), oacc);
            }
        }
        // red hazard: next write to red only after conv1+conv2 barriers of the
        // next net, which warp0 must also pass after its read above.
    }

    if (warp == 0 && lane < CV)
        atomicAdd(&out[b*CV + lane], oacc);
}

extern "C" void kernel_launch(void* const* d_in, const int* in_sizes, int n_in,
                              void* d_out, int out_size) {
    const int*   ids  = (const int*)  d_in[0];
    const float* mask = (const float*)d_in[1];
    const float* z    = (const float*)d_in[2];
    const float* emb  = (const float*)d_in[3];
    const float* W1   = (const float*)d_in[4];
    const float* b1   = (const float*)d_in[5];
    const float* W2   = (const float*)d_in[6];
    const float* b2   = (const float*)d_in[7];
    const float* W3   = (const float*)d_in[8];
    const float* b3   = (const float*)d_in[9];
    const float* Wh   = (const float*)d_in[10];
    const float* bh   = (const float*)d_in[11];
    float* out = (float*)d_out;

    repack_kernel<<<(DZV*192 + 255)/256, 256>>>(W1, W2, W3);
    float* scratch = nullptr;
    cudaGetSymbolAddress((void**)&scratch, g_wscratch);
    cudaMemcpyToSymbolAsync(cW1p, scratch,        DZV*96*sizeof(float),  0, cudaMemcpyDeviceToDevice, 0);
    cudaMemcpyToSymbolAsync(cW2p, scratch + 2880, DZV*96*sizeof(float),  0, cudaMemcpyDeviceToDevice, 0);
    cudaMemcpyToSymbolAsync(cW3p, scratch + 5760, DZV*192*sizeof(float), 0, cudaMemcpyDeviceToDevice, 0);
    // biases are already adjacent oc-pairs: copy raw floats into u64 symbols
    cudaMemcpyToSymbolAsync(cB1p, b1, DZV*4*sizeof(float),  0, cudaMemcpyDeviceToDevice, 0);
    cudaMemcpyToSymbolAsync(cB2p, b2, DZV*8*sizeof(float),  0, cudaMemcpyDeviceToDevice, 0);
    cudaMemcpyToSymbolAsync(cB3p, b3, DZV*8*sizeof(float),  0, cudaMemcpyDeviceToDevice, 0);
    cudaMemcpyToSymbolAsync(cWh, Wh, DZV*80*sizeof(float),  0, cudaMemcpyDeviceToDevice, 0);
    cudaMemcpyToSymbolAsync(cZ,  z,  DZV*sizeof(float),     0, cudaMemcpyDeviceToDevice, 0);

    init_out_kernel<<<(B_TOT*CV + 255)/256, 256>>>(z, bh, out);

    cudaFuncSetAttribute(ensemble_kernel,
                         cudaFuncAttributeMaxDynamicSharedMemorySize,
                         SMEM_FLOATS * (int)sizeof(float));
    ensemble_kernel<<<dim3(B_TOT, 2), NT, SMEM_FLOATS * (int)sizeof(float)>>>(ids, mask, emb, out);
}

// round 5
// speedup vs baseline: 1.2709x; 1.0690x over previous
#include <cuda_runtime.h>

#define NT 512
#define L_IN 4096
#define DZV 30
#define CV 10
#define NPG 15
#define B_TOT 512

typedef unsigned long long u64;

// ---- paired weights, 16B-vectorized for LDC.128 ----
// each ulonglong2 = two (oc_even, oc_odd) f32 pairs
__constant__ ulonglong2 cW1q[DZV*24];  // [d][ch<8][k<3]        -> (pr0, pr1)
__constant__ ulonglong2 cW2q[DZV*24];  // [d][ch<4][k<3][h<2]   -> (pr0,pr1),(pr2,pr3)
__constant__ ulonglong2 cW3q[DZV*48];  // [d][ch<8][k<3][h<2]
__constant__ ulonglong2 cB1q[DZV];     // (pr0, pr1)
__constant__ ulonglong2 cB2q[DZV*2];
__constant__ ulonglong2 cB3q[DZV*2];
__constant__ float cWh[DZV*80];        // [d][c][j]
__constant__ float cZ[DZV];

__device__ float g_wscratch[11520];

__device__ __forceinline__ u64 dup2(float v) {
    u64 r; asm("mov.b64 %0, {%1, %1};" : "=l"(r) : "f"(v)); return r;
}
__device__ __forceinline__ void unpack2(u64 v, float& lo, float& hi) {
    asm("mov.b64 {%0, %1}, %2;" : "=f"(lo), "=f"(hi) : "l"(v));
}
__device__ __forceinline__ u64 ffma2(u64 a, u64 b, u64 c) {
    u64 d; asm("fma.rn.f32x2 %0, %1, %2, %3;" : "=l"(d) : "l"(a), "l"(b), "l"(c)); return d;
}

// repack scalar conv weights into oc-paired float layout
__global__ void repack_kernel(const float* __restrict__ W1,
                              const float* __restrict__ W2,
                              const float* __restrict__ W3) {
    int i = blockIdx.x * blockDim.x + threadIdx.x;
    if (i < DZV*96) {   // W1p: dst ((d*8... dst (((d*8+... ((d)*8*3 ...): ((d*24 + ch*3 + k)*2 + pr)*... flat
        int d = i / 96, r = i % 96;
        int h = r & 1, pr = (r >> 1) & 1, k = (r >> 2) % 3, ch = (r >> 2) / 3;
        int oc = 2*pr + h;
        g_wscratch[i] = W1[d*96 + oc*24 + ch*3 + k];
    }
    if (i < DZV*96) {   // W2p: flat ((d*12 + ch*3+k)*4 + pr)*2-half
        int d = i / 96, r = i % 96;
        int h = r & 1, pr = (r >> 1) & 3, k = (r >> 3) % 3, ch = (r >> 3) / 3;
        int oc = 2*pr + h;
        g_wscratch[2880 + i] = W2[d*96 + oc*12 + ch*3 + k];
    }
    if (i < DZV*192) {  // W3p
        int d = i / 192, r = i % 192;
        int h = r & 1, pr = (r >> 1) & 3, k = (r >> 3) % 3, ch = (r >> 3) / 3;
        int oc = 2*pr + h;
        g_wscratch[5760 + i] = W3[d*192 + oc*24 + ch*3 + k];
    }
}

// out[b,c] = sum_d z[d]*bh[d,c]  (head bias folded here)
__global__ void init_out_kernel(const float* __restrict__ z,
                                const float* __restrict__ bh,
                                float* __restrict__ out) {
    int i = blockIdx.x * blockDim.x + threadIdx.x;
    if (i < B_TOT*CV) {
        int c = i % CV;
        float s = 0.f;
        #pragma unroll
        for (int d = 0; d < DZV; d++) s = fmaf(z[d], bh[d*CV + c], s);
        out[i] = s;
    }
}

// ---- smem layout: full sequence, 1 CTA/SM ----
#define XS_STR 4104
#define H1_STR 2056
#define H2_STR 1032
#define H1_OFF (8*XS_STR)                 // 32832
#define H2_OFF (H1_OFF + 4*H1_STR)        // 41056
#define RED_OFF (H2_OFF + 8*H2_STR)       // 49312
#define SMEM_FLOATS (RED_OFF + 136)       // 49448 floats = 197792 B

__global__ __launch_bounds__(NT, 1)
void ensemble_kernel(const int* __restrict__ ids,
                     const float* __restrict__ mask,
                     const float* __restrict__ embed,
                     float* __restrict__ out)
{
    extern __shared__ float sm[];
    float* xs  = sm;               // [8][XS_STR]
    float* h1  = sm + H1_OFF;      // [4][H1_STR]
    float* h2  = sm + H2_OFF;      // [8][H2_STR]
    float* red = sm + RED_OFF;     // [16 warps][8]

    const int tid  = threadIdx.x;
    const int lane = tid & 31;
    const int warp = tid >> 5;
    const int b    = blockIdx.x;
    const int g    = blockIdx.y;

    // zero the xs tail pad touched by the (discarded) OOB conv1 position
    if (tid < 8) {
        #pragma unroll
        for (int ch = 0; ch < 8; ch++) xs[ch*XS_STR + 4096 + tid] = 0.f;
    }

    // ---- gather masked embeddings, channel-major ----
    #pragma unroll 1
    for (int i = tid; i < L_IN; i += NT) {
        int   id = __ldg(&ids[b*L_IN + i]);
        float m  = __ldg(&mask[b*L_IN + i]);
        float4 e0 = __ldg((const float4*)(embed + (size_t)id*8));
        float4 e1 = __ldg((const float4*)(embed + (size_t)id*8 + 4));
        xs[0*XS_STR+i] = e0.x*m; xs[1*XS_STR+i] = e0.y*m;
        xs[2*XS_STR+i] = e0.z*m; xs[3*XS_STR+i] = e0.w*m;
        xs[4*XS_STR+i] = e1.x*m; xs[5*XS_STR+i] = e1.y*m;
        xs[6*XS_STR+i] = e1.z*m; xs[7*XS_STR+i] = e1.w*m;
    }
    __syncthreads();

    float oacc = 0.f;   // warp0, lane<CV

    #pragma unroll 1
    for (int dn = 0; dn < NPG; dn++) {
        const int d = g*NPG + dn;

        // ======== conv1: xs[8][4096] -> h1[4][2047], K3 S2 + ReLU ========
        // 4 positions/thread (512*4 = 2048; pos 2047 is dead pad)
        {
            const int r0 = tid * 4;
            const int ib = r0 * 2;
            u64 acc[4][2];
            {
                const ulonglong2 bb = cB1q[d];
                #pragma unroll
                for (int p = 0; p < 4; p++) { acc[p][0] = bb.x; acc[p][1] = bb.y; }
            }
            #pragma unroll
            for (int ch = 0; ch < 8; ch++) {
                const float* row = xs + ch*XS_STR + ib;
                float4 v0 = *(const float4*)row;
                float4 v1 = *(const float4*)(row + 4);
                float  v8 = row[8];
                u64 X[9];
                X[0]=dup2(v0.x); X[1]=dup2(v0.y); X[2]=dup2(v0.z); X[3]=dup2(v0.w);
                X[4]=dup2(v1.x); X[5]=dup2(v1.y); X[6]=dup2(v1.z); X[7]=dup2(v1.w);
                X[8]=dup2(v8);
                #pragma unroll
                for (int k = 0; k < 3; k++) {
                    const ulonglong2 w = cW1q[d*24 + ch*3 + k];   // LDC.128
                    #pragma unroll
                    for (int p = 0; p < 4; p++) {
                        const u64 x2 = X[2*p + k];
                        acc[p][0] = ffma2(w.x, x2, acc[p][0]);
                        acc[p][1] = ffma2(w.y, x2, acc[p][1]);
                    }
                }
            }
            float o[4][4];
            #pragma unroll
            for (int p = 0; p < 4; p++) {
                float a0,a1,a2,a3;
                unpack2(acc[p][0], a0, a1);
                unpack2(acc[p][1], a2, a3);
                o[p][0]=fmaxf(a0,0.f); o[p][1]=fmaxf(a1,0.f);
                o[p][2]=fmaxf(a2,0.f); o[p][3]=fmaxf(a3,0.f);
            }
            #pragma unroll
            for (int oc = 0; oc < 4; oc++)
                *(float4*)(h1 + oc*H1_STR + r0) =
                    make_float4(o[0][oc], o[1][oc], o[2][oc], o[3][oc]);
        }
        __syncthreads();

        // ======== conv2: h1[4][2047] -> h2[8][1023], K3 S2 + ReLU ========
        // 2 positions/thread (512*2 = 1024; pos 1023 dead pad)
        {
            const int q0 = tid * 2;
            const int ib = q0 * 2;
            u64 acc[2][4];
            {
                const ulonglong2 b0 = cB2q[d*2+0], b1 = cB2q[d*2+1];
                #pragma unroll
                for (int p = 0; p < 2; p++) {
                    acc[p][0] = b0.x; acc[p][1] = b0.y;
                    acc[p][2] = b1.x; acc[p][3] = b1.y;
                }
            }
            #pragma unroll
            for (int ch = 0; ch < 4; ch++) {
                const float* row = h1 + ch*H1_STR + ib;
                float4 v0 = *(const float4*)row;
                float  v4 = row[4];
                u64 X[5];
                X[0]=dup2(v0.x); X[1]=dup2(v0.y); X[2]=dup2(v0.z); X[3]=dup2(v0.w);
                X[4]=dup2(v4);
                #pragma unroll
                for (int k = 0; k < 3; k++) {
                    const ulonglong2 wa = cW2q[d*24 + (ch*3+k)*2 + 0]; // pr0, pr1
                    const ulonglong2 wb = cW2q[d*24 + (ch*3+k)*2 + 1]; // pr2, pr3
                    #pragma unroll
                    for (int p = 0; p < 2; p++) {
                        const u64 x2 = X[2*p + k];
                        acc[p][0] = ffma2(wa.x, x2, acc[p][0]);
                        acc[p][1] = ffma2(wa.y, x2, acc[p][1]);
                        acc[p][2] = ffma2(wb.x, x2, acc[p][2]);
                        acc[p][3] = ffma2(wb.y, x2, acc[p][3]);
                    }
                }
            }
            float o[2][8];
            #pragma unroll
            for (int p = 0; p < 2; p++)
                #pragma unroll
                for (int pr = 0; pr < 4; pr++) {
                    float lo, hi;
                    unpack2(acc[p][pr], lo, hi);
                    o[p][2*pr+0] = fmaxf(lo, 0.f);
                    o[p][2*pr+1] = fmaxf(hi, 0.f);
                }
            #pragma unroll
            for (int oc = 0; oc < 8; oc++)
                *(float2*)(h2 + oc*H2_STR + q0) = make_float2(o[0][oc], o[1][oc]);
        }
        __syncthreads();

        // ======== conv3 + ReLU + pool partial: h2[8][1023] -> psum[8] ========
        // 2 positions/thread (pos >= 1021 masked out of the pool)
        float psum[8];
        #pragma unroll
        for (int i = 0; i < 8; i++) psum[i] = 0.f;
        {
            const int p0 = tid * 2;
            u64 acc[2][4];
            {
                const ulonglong2 b0 = cB3q[d*2+0], b1 = cB3q[d*2+1];
                #pragma unroll
                for (int p = 0; p < 2; p++) {
                    acc[p][0] = b0.x; acc[p][1] = b0.y;
                    acc[p][2] = b1.x; acc[p][3] = b1.y;
                }
            }
            #pragma unroll
            for (int ch = 0; ch < 8; ch++) {
                const float* row = h2 + ch*H2_STR + p0;
                float2 a0 = *(const float2*)row;
                float2 a1 = *(const float2*)(row + 2);
                u64 X[4];
                X[0]=dup2(a0.x); X[1]=dup2(a0.y); X[2]=dup2(a1.x); X[3]=dup2(a1.y);
                #pragma unroll
                for (int k = 0; k < 3; k++) {
                    const ulonglong2 wa = cW3q[d*48 + (ch*3+k)*2 + 0];
                    const ulonglong2 wb = cW3q[d*48 + (ch*3+k)*2 + 1];
                    #pragma unroll
                    for (int p = 0; p < 2; p++) {
                        const u64 x2 = X[p + k];
                        acc[p][0] = ffma2(wa.x, x2, acc[p][0]);
                        acc[p][1] = ffma2(wa.y, x2, acc[p][1]);
                        acc[p][2] = ffma2(wb.x, x2, acc[p][2]);
                        acc[p][3] = ffma2(wb.y, x2, acc[p][3]);
                    }
                }
            }
            #pragma unroll
            for (int p = 0; p < 2; p++) {
                if (p0 + p < 1021) {
                    #pragma unroll
                    for (int pr = 0; pr < 4; pr++) {
                        float lo, hi;
                        unpack2(acc[p][pr], lo, hi);
                        psum[2*pr+0] += fmaxf(lo, 0.f);
                        psum[2*pr+1] += fmaxf(hi, 0.f);
                    }
                }
            }
        }

        // ---- warp reduce psum -> red[warp][oc] ----
        #pragma unroll
        for (int oc = 0; oc < 8; oc++) {
            float s = psum[oc];
            #pragma unroll
            for (int off = 16; off > 0; off >>= 1)
                s += __shfl_down_sync(0xFFFFFFFFu, s, off);
            if (lane == 0) red[warp*8 + oc] = s;
        }
        __syncthreads();

        // ---- warp0: cross-warp reduce (16 warps) + head matvec ----
        if (warp == 0) {
            float s = red[lane] + red[lane+32] + red[lane+64] + red[lane+96];
            s += __shfl_xor_sync(0xFFFFFFFFu, s, 8);
            s += __shfl_xor_sync(0xFFFFFFFFu, s, 16);
            float pj[8];
            #pragma unroll
            for (int j = 0; j < 8; j++)
                pj[j] = __shfl_sync(0xFFFFFFFFu, s, j);
            if (lane < CV) {
                float v = 0.f;
                #pragma unroll
                for (int j = 0; j < 8; j++)
                    v = fmaf(pj[j], cWh[(d*CV + lane)*8 + j], v);
                oacc = fmaf(v, cZ[d] * (1.0f/1021.0f), oacc);
            }
        }
        // red hazard: next write to red only after conv1+conv2 barriers of the
        // next net, which warp0 must also pass after its read above.
    }

    if (warp == 0 && lane < CV)
        atomicAdd(&out[b*CV + lane], oacc);
}

extern "C" void kernel_launch(void* const* d_in, const int* in_sizes, int n_in,
                              void* d_out, int out_size) {
    const int*   ids  = (const int*)  d_in[0];
    const float* mask = (const float*)d_in[1];
    const float* z    = (const float*)d_in[2];
    const float* emb  = (const float*)d_in[3];
    const float* W1   = (const float*)d_in[4];
    const float* b1   = (const float*)d_in[5];
    const float* W2   = (const float*)d_in[6];
    const float* b2   = (const float*)d_in[7];
    const float* W3   = (const float*)d_in[8];
    const float* b3   = (const float*)d_in[9];
    const float* Wh   = (const float*)d_in[10];
    const float* bh   = (const float*)d_in[11];
    float* out = (float*)d_out;

    repack_kernel<<<(DZV*192 + 255)/256, 256>>>(W1, W2, W3);
    float* scratch = nullptr;
    cudaGetSymbolAddress((void**)&scratch, g_wscratch);
    cudaMemcpyToSymbolAsync(cW1q, scratch,        DZV*96*sizeof(float),  0, cudaMemcpyDeviceToDevice, 0);
    cudaMemcpyToSymbolAsync(cW2q, scratch + 2880, DZV*96*sizeof(float),  0, cudaMemcpyDeviceToDevice, 0);
    cudaMemcpyToSymbolAsync(cW3q, scratch + 5760, DZV*192*sizeof(float), 0, cudaMemcpyDeviceToDevice, 0);
    // biases are already adjacent oc-pairs: copy raw floats
    cudaMemcpyToSymbolAsync(cB1q, b1, DZV*4*sizeof(float),  0, cudaMemcpyDeviceToDevice, 0);
    cudaMemcpyToSymbolAsync(cB2q, b2, DZV*8*sizeof(float),  0, cudaMemcpyDeviceToDevice, 0);
    cudaMemcpyToSymbolAsync(cB3q, b3, DZV*8*sizeof(float),  0, cudaMemcpyDeviceToDevice, 0);
    cudaMemcpyToSymbolAsync(cWh, Wh, DZV*80*sizeof(float),  0, cudaMemcpyDeviceToDevice, 0);
    cudaMemcpyToSymbolAsync(cZ,  z,  DZV*sizeof(float),     0, cudaMemcpyDeviceToDevice, 0);

    init_out_kernel<<<(B_TOT*CV + 255)/256, 256>>>(z, bh, out);

    cudaFuncSetAttribute(ensemble_kernel,
                         cudaFuncAttributeMaxDynamicSharedMemorySize,
                         SMEM_FLOATS * (int)sizeof(float));
    ensemble_kernel<<<dim3(B_TOT, 2), NT, SMEM_FLOATS * (int)sizeof(float)>>>(ids, mask, emb, out);
}